// round 11
// baseline (speedup 1.0000x reference)
#include <cuda_runtime.h>
#include <cstdint>

#define N_TOK  32768
#define KDIM   2048
#define NEXP   64
#define TOPK   6
#define TM     128             // tokens per CTA
#define KC     32              // K per staged chunk
#define NCHUNK (KDIM / KC)     // 64
#define LDROW  132             // padded smem row (floats): 16B-aligned rows

// dynamic smem: 2 stages x (As + Bd), each KC*LDROW floats
#define STAGE_F  (2 * KC * LDROW)             // floats per stage (As+Bd)
#define SMEM_BYTES (2 * STAGE_F * 4)

// ---- packed fp32x2 helpers (Blackwell FFMA2 path) ----
__device__ __forceinline__ unsigned long long fma2(unsigned long long a,
                                                   unsigned long long b,
                                                   unsigned long long c) {
    unsigned long long d;
    asm("fma.rn.f32x2 %0, %1, %2, %3;" : "=l"(d) : "l"(a), "l"(b), "l"(c));
    return d;
}
__device__ __forceinline__ float2 unpackff(unsigned long long v) {
    float2 f;
    asm("mov.b64 {%0, %1}, %2;" : "=f"(f.x), "=f"(f.y) : "l"(v));
    return f;
}

// FTZ emulation of XLA-GPU softmax tail (validated):
// exp below FLT_MIN -> 0.0; division result below FLT_MIN -> 0.0.
// Flushed experts tie at 0.0 -> top_k stable order = ascending index.
#define FLT_MIN_N 1.17549435082228751e-38f
__device__ __forceinline__ float exp_ftz(float x) {
    float e = expf(x);
    return (e < FLT_MIN_N) ? 0.0f : e;
}

// ============================================================
// Fused kernel: fp32 GEMM (128 tok x 64 exp per CTA, 8x8 thread
// tile, FFMA2, double-buffered smem) + softmax + top-6 epilogue.
// GEMM accumulation: single ascending-k FFMA.rn chain per element
// (bitwise identical scores to the validated kernel).
// out: [N_TOK*TOPK] weights fp32, then [N_TOK*TOPK] indices as fp32
// ============================================================
__global__ __launch_bounds__(128, 2)
void gate_fused_kernel(const float* __restrict__ x, const float* __restrict__ w,
                       float* __restrict__ out, int write_idx) {
    extern __shared__ float smem[];
    // stage s: As = smem + s*STAGE_F,  Bd = As + KC*LDROW
    const int tid = threadIdx.x;
    const int tx  = tid & 7;          // expert group (experts 8j+tx)
    const int ty  = tid >> 3;         // token group (tokens ty*8 .. +7)
    const int t0  = blockIdx.x * TM;

    unsigned long long acc[4][8];     // token pair p x expert group j
#pragma unroll
    for (int p = 0; p < 4; p++)
#pragma unroll
        for (int j = 0; j < 8; j++) acc[p][j] = 0ull;

    float4 ra[8], rb[4];
    // prefetch chunk 0
#pragma unroll
    for (int i = 0; i < 8; i++) {
        int gi = tid + 128 * i, row = gi >> 3, c16 = gi & 7;
        ra[i] = *(const float4*)(x + (size_t)(t0 + row) * KDIM + c16 * 4);
    }
#pragma unroll
    for (int i = 0; i < 4; i++) {
        int gi = tid + 128 * i, row = gi >> 3, c16 = gi & 7;
        rb[i] = *(const float4*)(w + (size_t)row * KDIM + c16 * 4);
    }
    // store chunk 0 into stage 0
    {
        float* As = smem;
        float* Bd = smem + KC * LDROW;
#pragma unroll
        for (int i = 0; i < 8; i++) {
            int gi = tid + 128 * i, row = gi >> 3, k4 = (gi & 7) * 4;
            As[(k4 + 0) * LDROW + row] = ra[i].x;
            As[(k4 + 1) * LDROW + row] = ra[i].y;
            As[(k4 + 2) * LDROW + row] = ra[i].z;
            As[(k4 + 3) * LDROW + row] = ra[i].w;
        }
#pragma unroll
        for (int i = 0; i < 4; i++) {
            int gi = tid + 128 * i, row = gi >> 3, k4 = (gi & 7) * 4;
            *(float2*)&Bd[(k4 + 0) * LDROW + 2 * row] = make_float2(rb[i].x, rb[i].x);
            *(float2*)&Bd[(k4 + 1) * LDROW + 2 * row] = make_float2(rb[i].y, rb[i].y);
            *(float2*)&Bd[(k4 + 2) * LDROW + 2 * row] = make_float2(rb[i].z, rb[i].z);
            *(float2*)&Bd[(k4 + 3) * LDROW + 2 * row] = make_float2(rb[i].w, rb[i].w);
        }
    }
    __syncthreads();

    for (int c = 0; c < NCHUNK; c++) {
        const float* As = smem + (c & 1) * STAGE_F;
        const float* Bd = As + KC * LDROW;

        // issue LDG for chunk c+1 (latency hidden behind compute)
        if (c + 1 < NCHUNK) {
            const int k0 = (c + 1) * KC;
#pragma unroll
            for (int i = 0; i < 8; i++) {
                int gi = tid + 128 * i, row = gi >> 3, c16 = gi & 7;
                ra[i] = *(const float4*)(x + (size_t)(t0 + row) * KDIM + k0 + c16 * 4);
            }
#pragma unroll
            for (int i = 0; i < 4; i++) {
                int gi = tid + 128 * i, row = gi >> 3, c16 = gi & 7;
                rb[i] = *(const float4*)(w + (size_t)row * KDIM + k0 + c16 * 4);
            }
        }

        // compute 32 ascending k-steps on stage (c&1)
#pragma unroll 8
        for (int kk = 0; kk < KC; kk++) {
            unsigned long long a[4], b[8];
            const float4 av0 = *(const float4*)&As[kk * LDROW + ty * 8];
            const float4 av1 = *(const float4*)&As[kk * LDROW + ty * 8 + 4];
            a[0] = *(const unsigned long long*)&av0.x;
            a[1] = *(const unsigned long long*)&av0.z;
            a[2] = *(const unsigned long long*)&av1.x;
            a[3] = *(const unsigned long long*)&av1.z;
#pragma unroll
            for (int j = 0; j < 8; j++)
                b[j] = *(const unsigned long long*)&Bd[kk * LDROW + 2 * (8 * j + tx)];
#pragma unroll
            for (int p = 0; p < 4; p++)
#pragma unroll
                for (int j = 0; j < 8; j++)
                    acc[p][j] = fma2(a[p], b[j], acc[p][j]);
        }

        // store chunk c+1 into the other stage (last read 1 chunk ago)
        if (c + 1 < NCHUNK) {
            float* As2 = smem + ((c + 1) & 1) * STAGE_F;
            float* Bd2 = As2 + KC * LDROW;
#pragma unroll
            for (int i = 0; i < 8; i++) {
                int gi = tid + 128 * i, row = gi >> 3, k4 = (gi & 7) * 4;
                As2[(k4 + 0) * LDROW + row] = ra[i].x;
                As2[(k4 + 1) * LDROW + row] = ra[i].y;
                As2[(k4 + 2) * LDROW + row] = ra[i].z;
                As2[(k4 + 3) * LDROW + row] = ra[i].w;
            }
#pragma unroll
            for (int i = 0; i < 4; i++) {
                int gi = tid + 128 * i, row = gi >> 3, k4 = (gi & 7) * 4;
                *(float2*)&Bd2[(k4 + 0) * LDROW + 2 * row] = make_float2(rb[i].x, rb[i].x);
                *(float2*)&Bd2[(k4 + 1) * LDROW + 2 * row] = make_float2(rb[i].y, rb[i].y);
                *(float2*)&Bd2[(k4 + 2) * LDROW + 2 * row] = make_float2(rb[i].z, rb[i].z);
                *(float2*)&Bd2[(k4 + 3) * LDROW + 2 * row] = make_float2(rb[i].w, rb[i].w);
            }
            __syncthreads();
        }
    }

    // ================= fused softmax + top-6 epilogue =================
    // Token t = t0 + ty*8 + tt is held by the 8 lanes sharing ty
    // (tx = lane bits 0..2): each lane owns experts {8j+tx : j=0..7}.
#pragma unroll
    for (int tt = 0; tt < 8; tt++) {
        const int t = t0 + ty * 8 + tt;
        float s[8];
#pragma unroll
        for (int j = 0; j < 8; j++) {
            float2 v = unpackff(acc[tt >> 1][j]);
            s[j] = (tt & 1) ? v.y : v.x;
        }
        // row max (exact, order-free)
        float m = s[0];
#pragma unroll
        for (int j = 1; j < 8; j++) m = fmaxf(m, s[j]);
#pragma unroll
        for (int o = 1; o <= 4; o <<= 1) m = fmaxf(m, __shfl_xor_sync(0xffffffffu, m, o));

        float e[8], sum = 0.0f;
#pragma unroll
        for (int j = 0; j < 8; j++) { e[j] = exp_ftz(s[j] - m); sum += e[j]; }
#pragma unroll
        for (int o = 1; o <= 4; o <<= 1) sum += __shfl_xor_sync(0xffffffffu, sum, o);

        float p[8];
#pragma unroll
        for (int j = 0; j < 8; j++) {
            p[j] = __fdiv_rn(e[j], sum);
            if (p[j] < FLT_MIN_N) p[j] = 0.0f;     // ftz division output
        }

        // top-6, tie -> smallest expert index (stable top_k order)
#pragma unroll
        for (int r = 0; r < TOPK; r++) {
            float bv = p[0]; int bj = 0;
#pragma unroll
            for (int j = 1; j < 8; j++)
                if (p[j] > bv) { bv = p[j]; bj = j; }   // strict > keeps smallest e locally
            int be = 8 * bj + tx;
#pragma unroll
            for (int o = 1; o <= 4; o <<= 1) {
                float ov = __shfl_xor_sync(0xffffffffu, bv, o);
                int   oe = __shfl_xor_sync(0xffffffffu, be, o);
                if (ov > bv || (ov == bv && oe < be)) { bv = ov; be = oe; }
            }
            if (tx == 0) {
                out[(size_t)t * TOPK + r] = bv;          // ROUTE_SCALE = 1
                if (write_idx)
                    out[(size_t)N_TOK * TOPK + (size_t)t * TOPK + r] = (float)be;
            }
            if ((be & 7) == tx) p[be >> 3] = -1.0f;      // eliminate winner
        }
    }
}

extern "C" void kernel_launch(void* const* d_in, const int* in_sizes, int n_in,
                              void* d_out, int out_size) {
    const float* x = (const float*)d_in[0];   // [32768, 2048] fp32
    const float* w = (const float*)d_in[1];   // [64, 2048] fp32
    float* out = (float*)d_out;

    static int smem_set = 0;
    if (!smem_set) {
        cudaFuncSetAttribute(gate_fused_kernel,
                             cudaFuncAttributeMaxDynamicSharedMemorySize, SMEM_BYTES);
        smem_set = 1;
    }
    const int write_idx = (out_size >= 2 * N_TOK * TOPK) ? 1 : 0;
    gate_fused_kernel<<<N_TOK / TM, 128, SMEM_BYTES>>>(x, w, out, write_idx);
}